// round 1
// baseline (speedup 1.0000x reference)
#include <cuda_runtime.h>
#include <math.h>

// ---------------------------------------------------------------------------
// ModelToVolumeAligner: rotate+offset 20480 atoms, splat 5-Gaussian mixture
// onto a 128^3 grid (voxel 1A), then 1 - cosine_similarity(vol, voxel_grid).
// Key insight: v/v.sum() normalization cancels in the cosine -> skip it.
// Gaussians truncated at exponent T=14 (relative e^-14 ~ 8e-7), radius
// R = sqrt(2*var*T) <= 7.49 voxels, window width <= 15.
// ---------------------------------------------------------------------------

#define NVOX (128 * 128 * 128)

__device__ float  g_vol[NVOX];
__device__ double g_acc[3];   // [0]=sum(v*g), [1]=sum(v*v), [2]=sum(g*g)

// --------------------------- zero scratch ----------------------------------
__global__ void mva_zero_kernel() {
    int stride = gridDim.x * blockDim.x;
    for (int i = blockIdx.x * blockDim.x + threadIdx.x; i < NVOX; i += stride)
        g_vol[i] = 0.0f;
    if (blockIdx.x == 0 && threadIdx.x < 3)
        g_acc[threadIdx.x] = 0.0;
}

// --------------------------- splat kernel ----------------------------------
// One warp per atom; 5 gaussians processed sequentially per warp.
// Per gaussian: 1D exp tables (z with prefactor folded in) in per-warp smem,
// then inner loop over (z serial, y pairs, x across 16 lanes) with predicated
// atomicAdd (REDG). Lanes (iy=lane>>4, ix=lane&15) -> 2 contiguous row
// segments per REDG (coalesced sectors).
__global__ void mva_splat_kernel(const float* __restrict__ quat,
                                 const float* __restrict__ offset,
                                 const float* __restrict__ pos,
                                 const float* __restrict__ amp,
                                 const float* __restrict__ var,
                                 int natoms) {
    __shared__ float s_tab[8][3][16];   // [warp][axis: 0=z,1=y,2=x][entry]

    const int gwarp  = (blockIdx.x * blockDim.x + threadIdx.x) >> 5;
    const int wl     = threadIdx.x >> 5;   // warp within block
    const int lane   = threadIdx.x & 31;
    if (gwarp >= natoms) return;

    // Quaternion -> rotation matrix (wxyz convention, normalized)
    float qw = quat[0], qx = quat[1], qy = quat[2], qz = quat[3];
    float qn = rsqrtf(qw * qw + qx * qx + qy * qy + qz * qz);
    qw *= qn; qx *= qn; qy *= qn; qz *= qn;
    const float r00 = 1.f - 2.f * (qy * qy + qz * qz);
    const float r01 = 2.f * (qx * qy - qw * qz);
    const float r02 = 2.f * (qx * qz + qw * qy);
    const float r10 = 2.f * (qx * qy + qw * qz);
    const float r11 = 1.f - 2.f * (qx * qx + qz * qz);
    const float r12 = 2.f * (qy * qz - qw * qx);
    const float r20 = 2.f * (qx * qz - qw * qy);
    const float r21 = 2.f * (qy * qz + qw * qx);
    const float r22 = 1.f - 2.f * (qx * qx + qy * qy);

    const float a0 = pos[gwarp * 3 + 0];
    const float a1 = pos[gwarp * 3 + 1];
    const float a2 = pos[gwarp * 3 + 2];
    // pos_rot = positions @ R + offset, then shift to grid coords (+64)
    const float px = a0 * r00 + a1 * r10 + a2 * r20 + offset[0] + 64.f;
    const float py = a0 * r01 + a1 * r11 + a2 * r21 + offset[1] + 64.f;
    const float pz = a0 * r02 + a1 * r12 + a2 * r22 + offset[2] + 64.f;

    const int ixl = lane & 15;
    const int iyl = lane >> 4;

    #pragma unroll 1
    for (int g = 0; g < 5; g++) {
        const float am    = amp[gwarp * 5 + g];
        const float vr    = var[gwarp * 5 + g];
        const float inv2v = 0.5f / vr;
        const float t     = 6.283185307179586f * vr;       // 2*pi*var
        const float pref  = am * rsqrtf(t * t * t);        // amp*(2pi v)^-1.5
        const float R     = sqrtf(28.f * vr);              // 2*var*T, T=14

        const int x0 = max(0, (int)ceilf(px - R));
        const int x1 = min(127, (int)floorf(px + R));
        const int y0 = max(0, (int)ceilf(py - R));
        const int y1 = min(127, (int)floorf(py + R));
        const int z0 = max(0, (int)ceilf(pz - R));
        const int z1 = min(127, (int)floorf(pz + R));
        const int wx = x1 - x0 + 1, wy = y1 - y0 + 1, wz = z1 - z0 + 1;
        if (wx <= 0 || wy <= 0 || wz <= 0) continue;

        // Build 1D tables (zero-padded to 16) — z carries the prefactor.
        if (lane < 16) {
            float dx = (float)(x0 + lane) - px;
            s_tab[wl][2][lane] = (lane < wx) ? __expf(-dx * dx * inv2v) : 0.f;
            float dy = (float)(y0 + lane) - py;
            s_tab[wl][1][lane] = (lane < wy) ? __expf(-dy * dy * inv2v) : 0.f;
            float dz = (float)(z0 + lane) - pz;
            s_tab[wl][0][lane] = (lane < wz) ? pref * __expf(-dz * dz * inv2v)
                                             : 0.f;
        }
        __syncwarp();

        // Spherical cutoff: keep contributions with total exponent <~ 14.5
        const float vmin = pref * 5.0434766e-7f;   // e^-14.5
        const float ex   = s_tab[wl][2][ixl];

        for (int iz = 0; iz < wz; iz++) {
            const float ez = s_tab[wl][0][iz];
            float* rowbase = g_vol + (z0 + iz) * 16384 + y0 * 128 + x0;
            #pragma unroll 2
            for (int iy0 = 0; iy0 < wy; iy0 += 2) {
                const int   iy  = iy0 + iyl;            // iy <= 15 always
                const float val = ez * s_tab[wl][1][iy] * ex;
                if (val > vmin)                          // zero-padded tables
                    atomicAdd(rowbase + iy * 128 + ixl, val);  // => REDG
            }
        }
        __syncwarp();
    }
}

// --------------------------- reduction -------------------------------------
__global__ void mva_reduce_kernel(const float* __restrict__ grid) {
    double vg = 0.0, vv = 0.0, gg = 0.0;
    const int stride = gridDim.x * blockDim.x;
    for (int i = blockIdx.x * blockDim.x + threadIdx.x; i < NVOX; i += stride) {
        const float v = g_vol[i];
        const float g = grid[i];
        vg += (double)v * (double)g;
        vv += (double)v * (double)v;
        gg += (double)g * (double)g;
    }
    // warp reduce
    #pragma unroll
    for (int o = 16; o > 0; o >>= 1) {
        vg += __shfl_down_sync(0xFFFFFFFFu, vg, o);
        vv += __shfl_down_sync(0xFFFFFFFFu, vv, o);
        gg += __shfl_down_sync(0xFFFFFFFFu, gg, o);
    }
    __shared__ double s[3][8];
    const int lane = threadIdx.x & 31, wid = threadIdx.x >> 5;
    if (lane == 0) { s[0][wid] = vg; s[1][wid] = vv; s[2][wid] = gg; }
    __syncthreads();
    if (wid == 0) {
        const int nw = blockDim.x >> 5;
        vg = (lane < nw) ? s[0][lane] : 0.0;
        vv = (lane < nw) ? s[1][lane] : 0.0;
        gg = (lane < nw) ? s[2][lane] : 0.0;
        #pragma unroll
        for (int o = 4; o > 0; o >>= 1) {
            vg += __shfl_down_sync(0xFFFFFFFFu, vg, o);
            vv += __shfl_down_sync(0xFFFFFFFFu, vv, o);
            gg += __shfl_down_sync(0xFFFFFFFFu, gg, o);
        }
        if (lane == 0) {
            atomicAdd(&g_acc[0], vg);
            atomicAdd(&g_acc[1], vv);
            atomicAdd(&g_acc[2], gg);
        }
    }
}

// --------------------------- finalize --------------------------------------
__global__ void mva_finalize_kernel(float* __restrict__ out) {
    // 1 - sum(v*g)/(||v|| * ||g||); v/v.sum() cancels exactly.
    const double vg = g_acc[0], vv = g_acc[1], gg = g_acc[2];
    out[0] = (float)(1.0 - vg / (sqrt(vv) * sqrt(gg)));
}

// --------------------------- launch ----------------------------------------
extern "C" void kernel_launch(void* const* d_in, const int* in_sizes, int n_in,
                              void* d_out, int out_size) {
    const float* quat    = (const float*)d_in[0];
    const float* offset  = (const float*)d_in[1];
    const float* pos     = (const float*)d_in[2];
    const float* amp     = (const float*)d_in[3];
    const float* var     = (const float*)d_in[4];
    const float* grid    = (const float*)d_in[5];
    float*       out     = (float*)d_out;

    const int natoms = in_sizes[2] / 3;   // 20480

    mva_zero_kernel<<<2048, 256>>>();

    const int warps_per_block = 8;
    const int nblocks = (natoms + warps_per_block - 1) / warps_per_block;
    mva_splat_kernel<<<nblocks, warps_per_block * 32>>>(quat, offset, pos,
                                                        amp, var, natoms);

    mva_reduce_kernel<<<1024, 256>>>(grid);
    mva_finalize_kernel<<<1, 1>>>(out);
}

// round 7
// speedup vs baseline: 1.8339x; 1.8339x over previous
#include <cuda_runtime.h>
#include <math.h>

// ---------------------------------------------------------------------------
// ModelToVolumeAligner: rotate+offset 20480 atoms, splat 5-Gaussian mixture
// onto 128^3 grid (voxel 1A), then 1 - cosine_similarity(vol, voxel_grid).
//   * v/v.sum() cancels in the cosine -> skipped.
//   * Merged pass: the 5 gaussians of an atom share a center -> ONE
//     union-window pass, per-voxel mixture value in registers, ONE atomic
//     per voxel (5x -> 1x atomic traffic; R1 kernel was L2-atomic bound).
//   * Truncation at exponent T=14 on the widest gaussian: R^2 = 28*var_max,
//     R <= 7.49 voxels, window <= 15 wide. Error ~e^-14 of peak ~ 8e-7.
//   * float4-vectorized zero + reduce kernels (fixed overhead trim).
// ---------------------------------------------------------------------------

#define NVOX (128 * 128 * 128)

__device__ float  g_vol[NVOX];
__device__ double g_acc[3];   // [0]=sum(v*g), [1]=sum(v*v), [2]=sum(g*g)

// --------------------------- zero scratch ----------------------------------
__global__ void mva_zero_kernel() {
    const int stride = gridDim.x * blockDim.x;
    float4* p = (float4*)g_vol;
    const float4 z = make_float4(0.f, 0.f, 0.f, 0.f);
    for (int i = blockIdx.x * blockDim.x + threadIdx.x; i < NVOX / 4; i += stride)
        p[i] = z;
    if (blockIdx.x == 0 && threadIdx.x < 3)
        g_acc[threadIdx.x] = 0.0;
}

// --------------------------- splat kernel ----------------------------------
// One warp per atom. Union window across the 5 gaussians. Per-axis 1D exp
// tables per gaussian in smem ([i][g] packed for LDS.128); z-table carries
// the (2*pi*var)^-1.5 * amp prefactor. Inner loop: lanes = (iy pair, 16 x),
// val = sum_g (ez_g*ex_g) * ey_g, single predicated atomicAdd (REDG).
__global__ void __launch_bounds__(256)
mva_splat_kernel(const float* __restrict__ quat,
                 const float* __restrict__ offset,
                 const float* __restrict__ pos,
                 const float* __restrict__ amp,
                 const float* __restrict__ var,
                 int natoms) {
    __shared__ __align__(16) float s_ex[8][5][16];   // [warp][g][ix]
    __shared__ __align__(16) float s_ey[8][16][8];   // [warp][iy][g(0..4)+pad]
    __shared__ __align__(16) float s_ez[8][16][8];   // [warp][iz][g(0..4)+pad]

    const int gwarp = (blockIdx.x * blockDim.x + threadIdx.x) >> 5;
    const int wl    = threadIdx.x >> 5;
    const int lane  = threadIdx.x & 31;
    if (gwarp >= natoms) return;

    // Quaternion -> rotation matrix (wxyz, normalized)
    float qw = quat[0], qx = quat[1], qy = quat[2], qz = quat[3];
    float qn = rsqrtf(qw * qw + qx * qx + qy * qy + qz * qz);
    qw *= qn; qx *= qn; qy *= qn; qz *= qn;
    const float a0 = pos[gwarp * 3 + 0];
    const float a1 = pos[gwarp * 3 + 1];
    const float a2 = pos[gwarp * 3 + 2];
    // pos_rot = positions @ R + offset, shifted to grid coords (+64)
    const float px = a0 * (1.f - 2.f * (qy * qy + qz * qz))
                   + a1 * (2.f * (qx * qy + qw * qz))
                   + a2 * (2.f * (qx * qz - qw * qy)) + offset[0] + 64.f;
    const float py = a0 * (2.f * (qx * qy - qw * qz))
                   + a1 * (1.f - 2.f * (qx * qx + qz * qz))
                   + a2 * (2.f * (qy * qz + qw * qx)) + offset[1] + 64.f;
    const float pz = a0 * (2.f * (qx * qz + qw * qy))
                   + a1 * (2.f * (qy * qz - qw * qx))
                   + a2 * (1.f - 2.f * (qx * qx + qy * qy)) + offset[2] + 64.f;

    // max variance across the 5 gaussians -> union radius
    float vm = (lane < 5) ? var[gwarp * 5 + lane] : 0.f;
    #pragma unroll
    for (int o = 4; o > 0; o >>= 1)
        vm = fmaxf(vm, __shfl_down_sync(0xFFFFFFFFu, vm, o));
    const float vmax = __shfl_sync(0xFFFFFFFFu, vm, 0);
    const float R2   = 28.f * vmax;           // 2*var_max*14
    const float R    = sqrtf(R2);

    const int x0 = max(0, (int)ceilf(px - R));
    const int x1 = min(127, (int)floorf(px + R));
    const int y0 = max(0, (int)ceilf(py - R));
    const int y1 = min(127, (int)floorf(py + R));
    const int z0 = max(0, (int)ceilf(pz - R));
    const int z1 = min(127, (int)floorf(pz + R));
    if (x0 > x1 || y0 > y1 || z0 > z1) return;

    // Build per-gaussian 1D tables over the (<=16 wide) union window.
    // 80 (g,i) pairs; z-table carries amp*(2*pi*var)^-1.5.
    for (int t = lane; t < 80; t += 32) {
        const int g = t >> 4, i = t & 15;
        const float vr    = var[gwarp * 5 + g];
        const float am    = amp[gwarp * 5 + g];
        const float inv2v = 0.5f / vr;
        const float tw    = 6.283185307179586f * vr;
        const float pref  = am * rsqrtf(tw * tw * tw);
        const float dx = (float)(x0 + i) - px;
        s_ex[wl][g][i] = __expf(-dx * dx * inv2v);
        const float dy = (float)(y0 + i) - py;
        s_ey[wl][i][g] = __expf(-dy * dy * inv2v);
        const float dz = (float)(z0 + i) - pz;
        s_ez[wl][i][g] = pref * __expf(-dz * dz * inv2v);
    }
    __syncwarp();

    const int   ixl  = lane & 15;
    const int   iyl  = lane >> 4;
    const bool  xin  = ixl <= (x1 - x0);
    const float dx   = (float)(x0 + ixl) - px;
    const float dx2  = dx * dx;

    const float ex0 = s_ex[wl][0][ixl];
    const float ex1 = s_ex[wl][1][ixl];
    const float ex2 = s_ex[wl][2][ixl];
    const float ex3 = s_ex[wl][3][ixl];
    const float ex4 = s_ex[wl][4][ixl];

    const int wz = z1 - z0 + 1;
    for (int iz = 0; iz < wz; iz++) {
        const float4 e4 = *(const float4*)&s_ez[wl][iz][0];
        const float  e5 = s_ez[wl][iz][4];
        const float az0 = e4.x * ex0, az1 = e4.y * ex1, az2 = e4.z * ex2;
        const float az3 = e4.w * ex3, az4 = e5   * ex4;

        const float dz  = (float)(z0 + iz) - pz;
        const float rz2 = fmaxf(R2 - dz * dz, 0.f);
        const float hw  = sqrtf(rz2);
        const int   ya  = max(y0, (int)ceilf(py - hw));
        const int   yb  = min(y1, (int)floorf(py + hw));

        float* slab = g_vol + (z0 + iz) * 16384 + x0 + ixl;
        for (int iy0 = ya; iy0 <= yb; iy0 += 2) {
            const int iy = iy0 + iyl;                 // iy - y0 <= 15 always
            const float4 y4 = *(const float4*)&s_ey[wl][iy - y0][0];
            const float  y5 = s_ey[wl][iy - y0][4];
            float v;
            v = az0 * y4.x;
            v = fmaf(az1, y4.y, v);
            v = fmaf(az2, y4.z, v);
            v = fmaf(az3, y4.w, v);
            v = fmaf(az4, y5,   v);
            const float dy = (float)iy - py;
            const float rr = fmaf(dy, dy, dx2);
            if (rr < rz2 && xin && iy <= yb)
                atomicAdd(slab + iy * 128, v);        // REDG
        }
    }
}

// --------------------------- reduction -------------------------------------
__global__ void mva_reduce_kernel(const float* __restrict__ grid) {
    double vg = 0.0, vv = 0.0, gg = 0.0;
    const int stride = gridDim.x * blockDim.x;
    const float4* pv = (const float4*)g_vol;
    const float4* pg = (const float4*)grid;
    for (int i = blockIdx.x * blockDim.x + threadIdx.x; i < NVOX / 4; i += stride) {
        const float4 v = pv[i];
        const float4 g = pg[i];
        vg += (double)v.x * g.x + (double)v.y * g.y
            + (double)v.z * g.z + (double)v.w * g.w;
        vv += (double)v.x * v.x + (double)v.y * v.y
            + (double)v.z * v.z + (double)v.w * v.w;
        gg += (double)g.x * g.x + (double)g.y * g.y
            + (double)g.z * g.z + (double)g.w * g.w;
    }
    #pragma unroll
    for (int o = 16; o > 0; o >>= 1) {
        vg += __shfl_down_sync(0xFFFFFFFFu, vg, o);
        vv += __shfl_down_sync(0xFFFFFFFFu, vv, o);
        gg += __shfl_down_sync(0xFFFFFFFFu, gg, o);
    }
    __shared__ double s[3][8];
    const int lane = threadIdx.x & 31, wid = threadIdx.x >> 5;
    if (lane == 0) { s[0][wid] = vg; s[1][wid] = vv; s[2][wid] = gg; }
    __syncthreads();
    if (wid == 0) {
        const int nw = blockDim.x >> 5;
        vg = (lane < nw) ? s[0][lane] : 0.0;
        vv = (lane < nw) ? s[1][lane] : 0.0;
        gg = (lane < nw) ? s[2][lane] : 0.0;
        #pragma unroll
        for (int o = 4; o > 0; o >>= 1) {
            vg += __shfl_down_sync(0xFFFFFFFFu, vg, o);
            vv += __shfl_down_sync(0xFFFFFFFFu, vv, o);
            gg += __shfl_down_sync(0xFFFFFFFFu, gg, o);
        }
        if (lane == 0) {
            atomicAdd(&g_acc[0], vg);
            atomicAdd(&g_acc[1], vv);
            atomicAdd(&g_acc[2], gg);
        }
    }
}

// --------------------------- finalize --------------------------------------
__global__ void mva_finalize_kernel(float* __restrict__ out) {
    const double vg = g_acc[0], vv = g_acc[1], gg = g_acc[2];
    out[0] = (float)(1.0 - vg / (sqrt(vv) * sqrt(gg)));
}

// --------------------------- launch ----------------------------------------
extern "C" void kernel_launch(void* const* d_in, const int* in_sizes, int n_in,
                              void* d_out, int out_size) {
    const float* quat   = (const float*)d_in[0];
    const float* offset = (const float*)d_in[1];
    const float* pos    = (const float*)d_in[2];
    const float* amp    = (const float*)d_in[3];
    const float* var    = (const float*)d_in[4];
    const float* grid   = (const float*)d_in[5];
    float*       out    = (float*)d_out;

    const int natoms = in_sizes[2] / 3;   // 20480

    mva_zero_kernel<<<1024, 256>>>();

    const int warps_per_block = 8;
    const int nblocks = (natoms + warps_per_block - 1) / warps_per_block;
    mva_splat_kernel<<<nblocks, warps_per_block * 32>>>(quat, offset, pos,
                                                        amp, var, natoms);

    mva_reduce_kernel<<<512, 256>>>(grid);
    mva_finalize_kernel<<<1, 1>>>(out);
}

// round 16
// speedup vs baseline: 1.9793x; 1.0793x over previous
#include <cuda_runtime.h>
#include <math.h>

// ---------------------------------------------------------------------------
// ModelToVolumeAligner: rotate+offset 20480 atoms, splat 5-Gaussian mixture
// onto 128^3 grid (voxel 1A), then 1 - cosine_similarity(vol, voxel_grid).
//   * v/v.sum() cancels in the cosine -> skipped.
//   * Merged pass: 5 gaussians/atom share a center -> ONE union-window pass,
//     mixture value in registers, ONE atomic per voxel.
//   * T=11 truncation (R^2 = 22*var_max): R7 showed rel_err bit-identical
//     across different effective cutoffs => truncation error below fp32
//     noise; e^-11 tail ~1.7e-5 of peak, >=100x inside the 1e-3 budget.
//   * NO zero kernel. g_vol is zero-initialized at load; the reduce
//     kernel re-zeroes it after reading, and the last block resets the
//     accumulators + ticket => invariant restored for every graph replay.
//     Launches: splat -> reduce+finalize (2 total).
// ---------------------------------------------------------------------------

#define NVOX (128 * 128 * 128)

__device__ float        g_vol[NVOX];      // zero-initialized at module load
__device__ double       g_acc[3];         // sum(v*g), sum(v*v), sum(g*g)
__device__ unsigned int g_bcount;         // reduce completion ticket

#define REDUCE_BLOCKS 512

// --------------------------- splat kernel ----------------------------------
// One warp per atom. Union window across the 5 gaussians. Per-axis 1D exp
// tables per gaussian in smem ([i][g] packed for LDS.128); z-table carries
// the (2*pi*var)^-1.5 * amp prefactor. Inner loop: lanes = (iy pair, 16 x),
// val = sum_g (ez_g*ex_g) * ey_g, single predicated atomicAdd (REDG).
__global__ void __launch_bounds__(256)
mva_splat_kernel(const float* __restrict__ quat,
                 const float* __restrict__ offset,
                 const float* __restrict__ pos,
                 const float* __restrict__ amp,
                 const float* __restrict__ var,
                 int natoms) {
    __shared__ __align__(16) float s_ex[8][5][16];   // [warp][g][ix]
    __shared__ __align__(16) float s_ey[8][16][8];   // [warp][iy][g(0..4)+pad]
    __shared__ __align__(16) float s_ez[8][16][8];   // [warp][iz][g(0..4)+pad]

    const int gwarp = (blockIdx.x * blockDim.x + threadIdx.x) >> 5;
    const int wl    = threadIdx.x >> 5;
    const int lane  = threadIdx.x & 31;
    if (gwarp >= natoms) return;

    // Quaternion -> rotation matrix (wxyz, normalized)
    float qw = quat[0], qx = quat[1], qy = quat[2], qz = quat[3];
    float qn = rsqrtf(qw * qw + qx * qx + qy * qy + qz * qz);
    qw *= qn; qx *= qn; qy *= qn; qz *= qn;
    const float a0 = pos[gwarp * 3 + 0];
    const float a1 = pos[gwarp * 3 + 1];
    const float a2 = pos[gwarp * 3 + 2];
    // pos_rot = positions @ R + offset, shifted to grid coords (+64)
    const float px = a0 * (1.f - 2.f * (qy * qy + qz * qz))
                   + a1 * (2.f * (qx * qy + qw * qz))
                   + a2 * (2.f * (qx * qz - qw * qy)) + offset[0] + 64.f;
    const float py = a0 * (2.f * (qx * qy - qw * qz))
                   + a1 * (1.f - 2.f * (qx * qx + qz * qz))
                   + a2 * (2.f * (qy * qz + qw * qx)) + offset[1] + 64.f;
    const float pz = a0 * (2.f * (qx * qz + qw * qy))
                   + a1 * (2.f * (qy * qz - qw * qx))
                   + a2 * (1.f - 2.f * (qx * qx + qy * qy)) + offset[2] + 64.f;

    // max variance across the 5 gaussians -> union radius
    float vm = (lane < 5) ? var[gwarp * 5 + lane] : 0.f;
    #pragma unroll
    for (int o = 4; o > 0; o >>= 1)
        vm = fmaxf(vm, __shfl_down_sync(0xFFFFFFFFu, vm, o));
    const float vmax = __shfl_sync(0xFFFFFFFFu, vm, 0);
    const float R2   = 22.f * vmax;           // 2*var_max*T, T=11
    const float R    = sqrtf(R2);

    const int x0 = max(0, (int)ceilf(px - R));
    const int x1 = min(127, (int)floorf(px + R));
    const int y0 = max(0, (int)ceilf(py - R));
    const int y1 = min(127, (int)floorf(py + R));
    const int z0 = max(0, (int)ceilf(pz - R));
    const int z1 = min(127, (int)floorf(pz + R));
    if (x0 > x1 || y0 > y1 || z0 > z1) return;

    // Build per-gaussian 1D tables over the (<=14 wide) union window.
    // 80 (g,i) pairs; z-table carries amp*(2*pi*var)^-1.5.
    for (int t = lane; t < 80; t += 32) {
        const int g = t >> 4, i = t & 15;
        const float vr    = var[gwarp * 5 + g];
        const float am    = amp[gwarp * 5 + g];
        const float inv2v = 0.5f / vr;
        const float tw    = 6.283185307179586f * vr;
        const float pref  = am * rsqrtf(tw * tw * tw);
        const float dx = (float)(x0 + i) - px;
        s_ex[wl][g][i] = __expf(-dx * dx * inv2v);
        const float dy = (float)(y0 + i) - py;
        s_ey[wl][i][g] = __expf(-dy * dy * inv2v);
        const float dz = (float)(z0 + i) - pz;
        s_ez[wl][i][g] = pref * __expf(-dz * dz * inv2v);
    }
    __syncwarp();

    const int   ixl  = lane & 15;
    const int   iyl  = lane >> 4;
    const bool  xin  = ixl <= (x1 - x0);
    const float dx   = (float)(x0 + ixl) - px;
    const float dx2  = dx * dx;

    const float ex0 = s_ex[wl][0][ixl];
    const float ex1 = s_ex[wl][1][ixl];
    const float ex2 = s_ex[wl][2][ixl];
    const float ex3 = s_ex[wl][3][ixl];
    const float ex4 = s_ex[wl][4][ixl];

    const int wz = z1 - z0 + 1;
    for (int iz = 0; iz < wz; iz++) {
        const float4 e4 = *(const float4*)&s_ez[wl][iz][0];
        const float  e5 = s_ez[wl][iz][4];
        const float az0 = e4.x * ex0, az1 = e4.y * ex1, az2 = e4.z * ex2;
        const float az3 = e4.w * ex3, az4 = e5   * ex4;

        const float dz  = (float)(z0 + iz) - pz;
        const float rz2 = fmaxf(R2 - dz * dz, 0.f);
        const float hw  = sqrtf(rz2);
        const int   ya  = max(y0, (int)ceilf(py - hw));
        const int   yb  = min(y1, (int)floorf(py + hw));

        float* slab = g_vol + (z0 + iz) * 16384 + x0 + ixl;
        for (int iy0 = ya; iy0 <= yb; iy0 += 2) {
            const int iy = iy0 + iyl;                 // iy - y0 <= 15 always
            const float4 y4 = *(const float4*)&s_ey[wl][iy - y0][0];
            const float  y5 = s_ey[wl][iy - y0][4];
            float v;
            v = az0 * y4.x;
            v = fmaf(az1, y4.y, v);
            v = fmaf(az2, y4.z, v);
            v = fmaf(az3, y4.w, v);
            v = fmaf(az4, y5,   v);
            const float dy = (float)iy - py;
            const float rr = fmaf(dy, dy, dx2);
            if (rr < rz2 && xin && iy <= yb)
                atomicAdd(slab + iy * 128, v);        // REDG
        }
    }
}

// --------- reduction + fused finalize + volume re-zero ----------------------
// Reads v (g_vol) and g (grid), accumulates the three dot products, and
// writes zeros back into g_vol so the next graph replay starts clean.
// The last block (ticket) computes the output scalar and resets the
// accumulators + ticket. All blocks' atomicAdds precede the last ticket
// increment, so the reset cannot race with accumulation.
__global__ void mva_reduce_kernel(const float* __restrict__ grid,
                                  float* __restrict__ out) {
    double vg = 0.0, vv = 0.0, gg = 0.0;
    const int stride = gridDim.x * blockDim.x;
    float4* pv = (float4*)g_vol;
    const float4* pg = (const float4*)grid;
    const float4 z4 = make_float4(0.f, 0.f, 0.f, 0.f);
    for (int i = blockIdx.x * blockDim.x + threadIdx.x; i < NVOX / 4; i += stride) {
        const float4 v = pv[i];
        const float4 g = pg[i];
        pv[i] = z4;                               // re-zero for next replay
        vg += (double)v.x * g.x + (double)v.y * g.y
            + (double)v.z * g.z + (double)v.w * g.w;
        vv += (double)v.x * v.x + (double)v.y * v.y
            + (double)v.z * v.z + (double)v.w * v.w;
        gg += (double)g.x * g.x + (double)g.y * g.y
            + (double)g.z * g.z + (double)g.w * g.w;
    }
    #pragma unroll
    for (int o = 16; o > 0; o >>= 1) {
        vg += __shfl_down_sync(0xFFFFFFFFu, vg, o);
        vv += __shfl_down_sync(0xFFFFFFFFu, vv, o);
        gg += __shfl_down_sync(0xFFFFFFFFu, gg, o);
    }
    __shared__ double s[3][8];
    const int lane = threadIdx.x & 31, wid = threadIdx.x >> 5;
    if (lane == 0) { s[0][wid] = vg; s[1][wid] = vv; s[2][wid] = gg; }
    __syncthreads();
    __shared__ bool s_last;
    if (wid == 0) {
        const int nw = blockDim.x >> 5;
        vg = (lane < nw) ? s[0][lane] : 0.0;
        vv = (lane < nw) ? s[1][lane] : 0.0;
        gg = (lane < nw) ? s[2][lane] : 0.0;
        #pragma unroll
        for (int o = 4; o > 0; o >>= 1) {
            vg += __shfl_down_sync(0xFFFFFFFFu, vg, o);
            vv += __shfl_down_sync(0xFFFFFFFFu, vv, o);
            gg += __shfl_down_sync(0xFFFFFFFFu, gg, o);
        }
        if (lane == 0) {
            atomicAdd(&g_acc[0], vg);
            atomicAdd(&g_acc[1], vv);
            atomicAdd(&g_acc[2], gg);
            __threadfence();
            const unsigned int t = atomicAdd(&g_bcount, 1u);
            s_last = (t == (unsigned int)(gridDim.x - 1));
        }
    }
    __syncthreads();
    // Last block: write the scalar, then reset accumulators + ticket so the
    // next graph replay starts from the load-time state.
    if (s_last && threadIdx.x == 0) {
        const double fvg = g_acc[0], fvv = g_acc[1], fgg = g_acc[2];
        out[0] = (float)(1.0 - fvg / (sqrt(fvv) * sqrt(fgg)));
        g_acc[0] = 0.0; g_acc[1] = 0.0; g_acc[2] = 0.0;
        g_bcount = 0u;
    }
}

// --------------------------- launch ----------------------------------------
extern "C" void kernel_launch(void* const* d_in, const int* in_sizes, int n_in,
                              void* d_out, int out_size) {
    const float* quat   = (const float*)d_in[0];
    const float* offset = (const float*)d_in[1];
    const float* pos    = (const float*)d_in[2];
    const float* amp    = (const float*)d_in[3];
    const float* var    = (const float*)d_in[4];
    const float* grid   = (const float*)d_in[5];
    float*       out    = (float*)d_out;

    const int natoms = in_sizes[2] / 3;   // 20480

    const int warps_per_block = 8;
    const int nblocks = (natoms + warps_per_block - 1) / warps_per_block;
    mva_splat_kernel<<<nblocks, warps_per_block * 32>>>(quat, offset, pos,
                                                        amp, var, natoms);

    mva_reduce_kernel<<<REDUCE_BLOCKS, 256>>>(grid, out);
}